// round 2
// baseline (speedup 1.0000x reference)
#include <cuda_runtime.h>
#include <cstddef>

// ---------------- scratch (device globals: no cudaMalloc allowed) ----------
__device__ float g_q[4u * 1024u * 1024u];        // q, later reused as ctx
__device__ float g_k[4u * 1024u * 1024u];
__device__ float g_v[4u * 1024u * 1024u];
__device__ float g_scores[64u * 1024u * 1024u];  // [B*N, S, S] = 256 MB

// ---------------------------------------------------------------------------
// Kernel 1/5: C[4096,1024] = A[4096,1024] @ W[1024,1024] + bias[1024]
// 128x128 block tile, BK=16, 256 threads, 8x8 per thread.
// ---------------------------------------------------------------------------
__global__ __launch_bounds__(256, 2)
void sgemm_bias_k(const float* __restrict__ A, const float* __restrict__ W,
                  const float* __restrict__ bias, float* __restrict__ C) {
    __shared__ float As[16][128];   // [k][m] (transposed on load)
    __shared__ float Bs[16][128];   // [k][n]
    const int tid = threadIdx.x;
    const int tx = tid & 15;        // 0..15 -> 8 cols each
    const int ty = tid >> 4;        // 0..15 -> 8 rows each
    const int row0 = blockIdx.y * 128;
    const int col0 = blockIdx.x * 128;

    float acc[8][8];
#pragma unroll
    for (int i = 0; i < 8; i++)
#pragma unroll
        for (int j = 0; j < 8; j++) acc[i][j] = 0.0f;

    for (int k0 = 0; k0 < 1024; k0 += 16) {
        // load A tile 128x16: 512 float4, 2 per thread, store transposed
#pragma unroll
        for (int l = 0; l < 2; l++) {
            int i = tid + l * 256;
            int r = i >> 2, kq = (i & 3) << 2;
            float4 v = *(const float4*)(A + (size_t)(row0 + r) * 1024 + k0 + kq);
            As[kq + 0][r] = v.x; As[kq + 1][r] = v.y;
            As[kq + 2][r] = v.z; As[kq + 3][r] = v.w;
        }
        // load W tile 16x128: 512 float4, natural layout
#pragma unroll
        for (int l = 0; l < 2; l++) {
            int i = tid + l * 256;
            int r = i >> 5, nq = (i & 31) << 2;
            *(float4*)(&Bs[r][nq]) =
                *(const float4*)(W + (size_t)(k0 + r) * 1024 + col0 + nq);
        }
        __syncthreads();
#pragma unroll
        for (int kk = 0; kk < 16; kk++) {
            float a[8], b[8];
            *(float4*)(a)     = *(float4*)(&As[kk][ty * 8]);
            *(float4*)(a + 4) = *(float4*)(&As[kk][ty * 8 + 4]);
            *(float4*)(b)     = *(float4*)(&Bs[kk][tx * 8]);
            *(float4*)(b + 4) = *(float4*)(&Bs[kk][tx * 8 + 4]);
#pragma unroll
            for (int i = 0; i < 8; i++)
#pragma unroll
                for (int j = 0; j < 8; j++) acc[i][j] = fmaf(a[i], b[j], acc[i][j]);
        }
        __syncthreads();
    }

    float bv[8];
    *(float4*)(bv)     = *(const float4*)(bias + col0 + tx * 8);
    *(float4*)(bv + 4) = *(const float4*)(bias + col0 + tx * 8 + 4);
#pragma unroll
    for (int i = 0; i < 8; i++) {
        float4 o0, o1;
        o0.x = acc[i][0] + bv[0]; o0.y = acc[i][1] + bv[1];
        o0.z = acc[i][2] + bv[2]; o0.w = acc[i][3] + bv[3];
        o1.x = acc[i][4] + bv[4]; o1.y = acc[i][5] + bv[5];
        o1.z = acc[i][6] + bv[6]; o1.w = acc[i][7] + bv[7];
        float* cp = C + (size_t)(row0 + ty * 8 + i) * 1024 + col0 + tx * 8;
        *(float4*)(cp)     = o0;
        *(float4*)(cp + 4) = o1;
    }
}

// ---------------------------------------------------------------------------
// Kernel 2: scores[b,n,f,t] = (1/8) * sum_h q[b,f,n,h] * k[b,t,n,h]
// per (b,n): 1024x1024 GEMM, K=64. 64x64 block tile, 4x4 per thread.
// ---------------------------------------------------------------------------
__global__ __launch_bounds__(256)
void qk_kernel() {
    __shared__ float Qs[64][65];
    __shared__ float Ks[64][65];
    const int tid = threadIdx.x;
    const int tx = tid & 15, ty = tid >> 4;
    const int z = blockIdx.z;          // b*16 + n
    const int b = z >> 4, n = z & 15;
    const int f0 = blockIdx.y * 64, t0 = blockIdx.x * 64;

    const float* qb = g_q + ((size_t)(b * 1024 + f0) * 16 + n) * 64;
    const float* kb = g_k + ((size_t)(b * 1024 + t0) * 16 + n) * 64;

#pragma unroll
    for (int l = 0; l < 4; l++) {
        int i = tid + l * 256;
        int r = i >> 4, hq = (i & 15) << 2;
        float4 v = *(const float4*)(qb + (size_t)r * 1024 + hq);
        Qs[r][hq + 0] = v.x; Qs[r][hq + 1] = v.y;
        Qs[r][hq + 2] = v.z; Qs[r][hq + 3] = v.w;
        float4 w = *(const float4*)(kb + (size_t)r * 1024 + hq);
        Ks[r][hq + 0] = w.x; Ks[r][hq + 1] = w.y;
        Ks[r][hq + 2] = w.z; Ks[r][hq + 3] = w.w;
    }
    __syncthreads();

    float acc[4][4];
#pragma unroll
    for (int i = 0; i < 4; i++)
#pragma unroll
        for (int j = 0; j < 4; j++) acc[i][j] = 0.0f;

#pragma unroll
    for (int kk = 0; kk < 64; kk++) {
        float a[4], bb[4];
#pragma unroll
        for (int i = 0; i < 4; i++) a[i] = Qs[ty * 4 + i][kk];
#pragma unroll
        for (int j = 0; j < 4; j++) bb[j] = Ks[tx * 4 + j][kk];
#pragma unroll
        for (int i = 0; i < 4; i++)
#pragma unroll
            for (int j = 0; j < 4; j++) acc[i][j] = fmaf(a[i], bb[j], acc[i][j]);
    }

    float* cb = g_scores + ((size_t)z * 1024 + f0) * 1024 + t0;
#pragma unroll
    for (int i = 0; i < 4; i++) {
        float4 o;
        o.x = acc[i][0] * 0.125f; o.y = acc[i][1] * 0.125f;
        o.z = acc[i][2] * 0.125f; o.w = acc[i][3] * 0.125f;
        *(float4*)(cb + (size_t)(ty * 4 + i) * 1024 + tx * 4) = o;
    }
}

// ---------------------------------------------------------------------------
// Kernel 3: fused premix -> mask -> softmax -> postmix, in place on g_scores.
// One block per (b,f). Holds all 16 heads' rows of length 1024 in smem.
// Row stride 1028 (pad) keeps column gathers conflict-free.
// ---------------------------------------------------------------------------
#define SW 1028
__global__ __launch_bounds__(256)
void mix_softmax_kernel(const int* __restrict__ amask,
                        const float* __restrict__ pre,
                        const float* __restrict__ post) {
    extern __shared__ float s[];           // 16 * SW floats
    __shared__ float wpre[256], wpost[256], sinv[16];
    const int tid = threadIdx.x;
    const int f = blockIdx.x, b = blockIdx.y;

    wpre[tid]  = pre[tid];
    wpost[tid] = post[tid];

    const size_t rowbase = ((size_t)(b * 16) * 1024 + f) * 1024;

    // load all 16 head-rows (each 1024 floats = 256 float4)
#pragma unroll
    for (int n = 0; n < 16; n++) {
        float4 v = *(const float4*)(g_scores + rowbase + (size_t)n * 1048576 + tid * 4);
        *(float4*)(&s[n * SW + tid * 4]) = v;
    }
    __syncthreads();

    // premix (nl contraction) + additive mask, column-wise in place
    const int* mrow = amask + ((size_t)b * 1024 + f) * 1024;
#pragma unroll
    for (int c = 0; c < 4; c++) {
        int t = tid + c * 256;
        float x[16];
#pragma unroll
        for (int n = 0; n < 16; n++) x[n] = s[n * SW + t];
        float madd = (1.0f - (float)mrow[t]) * -10000.0f;
#pragma unroll
        for (int l = 0; l < 16; l++) {
            float y = madd;
#pragma unroll
            for (int n = 0; n < 16; n++) y = fmaf(x[n], wpre[n * 16 + l], y);
            s[l * SW + t] = y;
        }
    }
    __syncthreads();

    // softmax over t for each of 16 rows; 8 warps x 2 rows.
    // store unnormalized exp, keep 1/sum in sinv[].
    const int warp = tid >> 5, lane = tid & 31;
#pragma unroll
    for (int r = 0; r < 2; r++) {
        int l = warp * 2 + r;
        float m = -1e30f;
        for (int it = lane; it < 1024; it += 32) m = fmaxf(m, s[l * SW + it]);
#pragma unroll
        for (int o = 16; o > 0; o >>= 1) m = fmaxf(m, __shfl_xor_sync(0xffffffffu, m, o));
        float sum = 0.0f;
        for (int it = lane; it < 1024; it += 32) {
            float e = __expf(s[l * SW + it] - m);
            s[l * SW + it] = e;
            sum += e;
        }
#pragma unroll
        for (int o = 16; o > 0; o >>= 1) sum += __shfl_xor_sync(0xffffffffu, sum, o);
        if (lane == 0) sinv[l] = 1.0f / sum;
    }
    __syncthreads();

    // postmix (fold 1/sum) and write probs back to global, column-wise
#pragma unroll
    for (int c = 0; c < 4; c++) {
        int t = tid + c * 256;
        float x[16];
#pragma unroll
        for (int n = 0; n < 16; n++) x[n] = s[n * SW + t] * sinv[n];
#pragma unroll
        for (int l = 0; l < 16; l++) {
            float y = 0.0f;
#pragma unroll
            for (int n = 0; n < 16; n++) y = fmaf(x[n], wpost[n * 16 + l], y);
            g_scores[rowbase + (size_t)l * 1048576 + t] = y;
        }
    }
}

// ---------------------------------------------------------------------------
// Kernel 4: ctx[b,f,n,h] = sum_t probs[b,n,f,t] * v[b,t,n,h]
// per (b,n): M=1024(f), N=64(h), K=1024(t). 64x64 tile, BK=32, 4x4/thread.
// ctx written over g_q (q is dead after kernel 2).
// ---------------------------------------------------------------------------
__global__ __launch_bounds__(256)
void pv_kernel() {
    __shared__ float Ps[64][33];
    __shared__ float Vs[32][64];
    const int tid = threadIdx.x;
    const int tx = tid & 15, ty = tid >> 4;
    const int z = blockIdx.y, b = z >> 4, n = z & 15;
    const int f0 = blockIdx.x * 64;

    const float* pb = g_scores + ((size_t)z * 1024 + f0) * 1024;
    const float* vb = g_v + ((size_t)b * 1024 * 16 + n) * 64;   // + t*1024 + h

    float acc[4][4];
#pragma unroll
    for (int i = 0; i < 4; i++)
#pragma unroll
        for (int j = 0; j < 4; j++) acc[i][j] = 0.0f;

    for (int k0 = 0; k0 < 1024; k0 += 32) {
#pragma unroll
        for (int l = 0; l < 2; l++) {
            int i = tid + l * 256;
            int r = i >> 3, tq = (i & 7) << 2;
            float4 v = *(const float4*)(pb + (size_t)r * 1024 + k0 + tq);
            Ps[r][tq + 0] = v.x; Ps[r][tq + 1] = v.y;
            Ps[r][tq + 2] = v.z; Ps[r][tq + 3] = v.w;
        }
#pragma unroll
        for (int l = 0; l < 2; l++) {
            int i = tid + l * 256;
            int r = i >> 4, hq = (i & 15) << 2;
            *(float4*)(&Vs[r][hq]) =
                *(const float4*)(vb + (size_t)(k0 + r) * 1024 + hq);
        }
        __syncthreads();
#pragma unroll
        for (int kk = 0; kk < 32; kk++) {
            float a[4];
#pragma unroll
            for (int i = 0; i < 4; i++) a[i] = Ps[ty * 4 + i][kk];
            float4 bv4 = *(float4*)(&Vs[kk][tx * 4]);
#pragma unroll
            for (int i = 0; i < 4; i++) {
                acc[i][0] = fmaf(a[i], bv4.x, acc[i][0]);
                acc[i][1] = fmaf(a[i], bv4.y, acc[i][1]);
                acc[i][2] = fmaf(a[i], bv4.z, acc[i][2]);
                acc[i][3] = fmaf(a[i], bv4.w, acc[i][3]);
            }
        }
        __syncthreads();
    }

    float* cb = g_q + ((size_t)(b * 1024 + f0) * 16 + n) * 64;
#pragma unroll
    for (int i = 0; i < 4; i++) {
        float4 o;
        o.x = acc[i][0]; o.y = acc[i][1]; o.z = acc[i][2]; o.w = acc[i][3];
        *(float4*)(cb + (size_t)(ty * 4 + i) * 1024 + tx * 4) = o;
    }
}

// ---------------------------------------------------------------------------
extern "C" void kernel_launch(void* const* d_in, const int* in_sizes, int n_in,
                              void* d_out, int out_size) {
    const float* from  = (const float*)d_in[0];
    const float* to    = (const float*)d_in[1];
    const int*   amask = (const int*)d_in[2];
    const float* wq    = (const float*)d_in[3];
    const float* bq    = (const float*)d_in[4];
    const float* wk    = (const float*)d_in[5];
    const float* bk    = (const float*)d_in[6];
    const float* wv    = (const float*)d_in[7];
    const float* bv    = (const float*)d_in[8];
    const float* pre   = (const float*)d_in[9];
    const float* post  = (const float*)d_in[10];
    const float* wo    = (const float*)d_in[11];
    const float* bo    = (const float*)d_in[12];
    float* out = (float*)d_out;

    float *qp = nullptr, *kp = nullptr, *vp = nullptr;
    cudaGetSymbolAddress((void**)&qp, g_q);
    cudaGetSymbolAddress((void**)&kp, g_k);
    cudaGetSymbolAddress((void**)&vp, g_v);

    cudaFuncSetAttribute(mix_softmax_kernel,
                         cudaFuncAttributeMaxDynamicSharedMemorySize,
                         16 * SW * (int)sizeof(float));

    dim3 gG(8, 32);                         // N/128 x M/128
    sgemm_bias_k<<<gG, 256>>>(from, wq, bq, qp);
    sgemm_bias_k<<<gG, 256>>>(to,   wk, bk, kp);
    sgemm_bias_k<<<gG, 256>>>(to,   wv, bv, vp);

    qk_kernel<<<dim3(16, 16, 64), 256>>>();

    mix_softmax_kernel<<<dim3(1024, 4), 256, 16 * SW * (int)sizeof(float)>>>(
        amask, pre, post);

    pv_kernel<<<dim3(16, 64), 256>>>();

    sgemm_bias_k<<<gG, 256>>>(qp, wo, bo, out);
}

// round 3
// speedup vs baseline: 1.1857x; 1.1857x over previous
#include <cuda_runtime.h>
#include <cuda_bf16.h>
#include <cstdint>
#include <cstddef>

// ---------------- scratch (device globals: no cudaMalloc allowed) ----------
__device__ float g_q[4u * 1024u * 1024u];        // q, later reused as ctx
__device__ float g_k[4u * 1024u * 1024u];
__device__ float g_v[4u * 1024u * 1024u];
__device__ float g_scores[64u * 1024u * 1024u];  // [B*N, S, S] = 256 MB

// ---------------------------------------------------------------------------
// PTX helpers (Ampere-class mma.sync on sm_103a tensor pipe)
// ---------------------------------------------------------------------------
__device__ __forceinline__ uint32_t smem_u32(const void* p) {
    return (uint32_t)__cvta_generic_to_shared(p);
}
__device__ __forceinline__ void ldsm_x4(uint32_t* r, uint32_t addr) {
    asm volatile("ldmatrix.sync.aligned.m8n8.x4.shared.b16 {%0,%1,%2,%3}, [%4];"
                 : "=r"(r[0]), "=r"(r[1]), "=r"(r[2]), "=r"(r[3]) : "r"(addr));
}
__device__ __forceinline__ void ldsm_x4_t(uint32_t* r, uint32_t addr) {
    asm volatile("ldmatrix.sync.aligned.m8n8.x4.trans.shared.b16 {%0,%1,%2,%3}, [%4];"
                 : "=r"(r[0]), "=r"(r[1]), "=r"(r[2]), "=r"(r[3]) : "r"(addr));
}
__device__ __forceinline__ void mma_bf16(float* c, const uint32_t* a, const uint32_t* b) {
    asm volatile(
        "mma.sync.aligned.m16n8k16.row.col.f32.bf16.bf16.f32 "
        "{%0,%1,%2,%3}, {%4,%5,%6,%7}, {%8,%9}, {%0,%1,%2,%3};"
        : "+f"(c[0]), "+f"(c[1]), "+f"(c[2]), "+f"(c[3])
        : "r"(a[0]), "r"(a[1]), "r"(a[2]), "r"(a[3]), "r"(b[0]), "r"(b[1]));
}
__device__ __forceinline__ void split_bf16(float x, __nv_bfloat16& h, __nv_bfloat16& l) {
    h = __float2bfloat16(x);
    l = __float2bfloat16(x - __bfloat162float(h));
}

// ---------------------------------------------------------------------------
// Kernel 1/5 (tensor-core): C[4096,1024] = A[4096,1024] @ W[1024,1024] + bias
// bf16x3 split (hi*hi + hi*lo + lo*hi), fp32 accumulate.
// Block tile 128x128, BK=32, 256 threads = 8 warps (4m x 2n), warp tile 32x64.
// ---------------------------------------------------------------------------
__global__ __launch_bounds__(256, 2)
void mma_gemm_bias(const float* __restrict__ A, const float* __restrict__ W,
                   const float* __restrict__ bias, float* __restrict__ C) {
    __shared__ __align__(16) __nv_bfloat16 sAhi[128][40];   // [m][k], pad->stride 40
    __shared__ __align__(16) __nv_bfloat16 sAlo[128][40];
    __shared__ __align__(16) __nv_bfloat16 sBhi[32][136];   // [k][n], pad->stride 136
    __shared__ __align__(16) __nv_bfloat16 sBlo[32][136];

    const int tid  = threadIdx.x;
    const int lane = tid & 31;
    const int warp = tid >> 5;
    const int wm   = warp >> 1;          // 0..3 -> m offset wm*32
    const int wn   = warp & 1;           // 0..1 -> n offset wn*64
    const int row0 = blockIdx.y * 128;
    const int col0 = blockIdx.x * 128;

    float c[2][8][4];
#pragma unroll
    for (int i = 0; i < 2; i++)
#pragma unroll
        for (int j = 0; j < 8; j++)
#pragma unroll
            for (int q = 0; q < 4; q++) c[i][j][q] = 0.0f;

    const int a_lrow = lane & 15;            // ldmatrix row within 16
    const int a_koff = (lane >> 4) << 3;     // 0 or 8

    for (int k0 = 0; k0 < 1024; k0 += 32) {
        // ---- stage A tile 128x32 (fp32 -> split bf16) ----
#pragma unroll
        for (int l = 0; l < 4; l++) {
            int idx = tid + l * 256;
            int m = idx >> 3, kq = (idx & 7) << 2;
            float4 v = *(const float4*)(A + (size_t)(row0 + m) * 1024 + k0 + kq);
            __nv_bfloat16 h0, h1, h2, h3, l0, l1, l2, l3;
            split_bf16(v.x, h0, l0); split_bf16(v.y, h1, l1);
            split_bf16(v.z, h2, l2); split_bf16(v.w, h3, l3);
            *(__nv_bfloat162*)&sAhi[m][kq]     = __halves2bfloat162(h0, h1);
            *(__nv_bfloat162*)&sAhi[m][kq + 2] = __halves2bfloat162(h2, h3);
            *(__nv_bfloat162*)&sAlo[m][kq]     = __halves2bfloat162(l0, l1);
            *(__nv_bfloat162*)&sAlo[m][kq + 2] = __halves2bfloat162(l2, l3);
        }
        // ---- stage B tile 32x128 ----
#pragma unroll
        for (int l = 0; l < 4; l++) {
            int idx = tid + l * 256;
            int k = idx >> 5, nq = (idx & 31) << 2;
            float4 v = *(const float4*)(W + (size_t)(k0 + k) * 1024 + col0 + nq);
            __nv_bfloat16 h0, h1, h2, h3, l0, l1, l2, l3;
            split_bf16(v.x, h0, l0); split_bf16(v.y, h1, l1);
            split_bf16(v.z, h2, l2); split_bf16(v.w, h3, l3);
            *(__nv_bfloat162*)&sBhi[k][nq]     = __halves2bfloat162(h0, h1);
            *(__nv_bfloat162*)&sBhi[k][nq + 2] = __halves2bfloat162(h2, h3);
            *(__nv_bfloat162*)&sBlo[k][nq]     = __halves2bfloat162(l0, l1);
            *(__nv_bfloat162*)&sBlo[k][nq + 2] = __halves2bfloat162(l2, l3);
        }
        __syncthreads();

#pragma unroll
        for (int ks = 0; ks < 2; ks++) {   // two k16 steps per k32
            uint32_t a_hi[2][4], a_lo[2][4];
#pragma unroll
            for (int mf = 0; mf < 2; mf++) {
                int mr = wm * 32 + mf * 16 + a_lrow;
                int kc = ks * 16 + a_koff;
                ldsm_x4(a_hi[mf], smem_u32(&sAhi[mr][kc]));
                ldsm_x4(a_lo[mf], smem_u32(&sAlo[mr][kc]));
            }
#pragma unroll
            for (int g = 0; g < 4; g++) {  // 4 n16-groups -> n 64
                uint32_t b_hi[4], b_lo[4];
                int kr = ks * 16 + a_lrow;
                int nc = wn * 64 + g * 16 + a_koff;
                ldsm_x4_t(b_hi, smem_u32(&sBhi[kr][nc]));
                ldsm_x4_t(b_lo, smem_u32(&sBlo[kr][nc]));
#pragma unroll
                for (int half = 0; half < 2; half++) {
                    int nf = g * 2 + half;
                    const uint32_t* bh = &b_hi[half * 2];
                    const uint32_t* bl = &b_lo[half * 2];
#pragma unroll
                    for (int mf = 0; mf < 2; mf++) {
                        mma_bf16(c[mf][nf], a_hi[mf], bh);   // hi*hi
                        mma_bf16(c[mf][nf], a_hi[mf], bl);   // hi*lo
                        mma_bf16(c[mf][nf], a_lo[mf], bh);   // lo*hi
                    }
                }
            }
        }
        __syncthreads();
    }

    // ---- epilogue: bias + store ----
    const int rbase = row0 + wm * 32 + (lane >> 2);
    const int cbase = col0 + wn * 64 + (lane & 3) * 2;
#pragma unroll
    for (int mf = 0; mf < 2; mf++) {
#pragma unroll
        for (int nf = 0; nf < 8; nf++) {
            int r = rbase + mf * 16;
            int cc = cbase + nf * 8;
            float2 bv = *(const float2*)(bias + cc);
            float2 o0 = make_float2(c[mf][nf][0] + bv.x, c[mf][nf][1] + bv.y);
            float2 o1 = make_float2(c[mf][nf][2] + bv.x, c[mf][nf][3] + bv.y);
            *(float2*)(C + (size_t)r * 1024 + cc)       = o0;
            *(float2*)(C + (size_t)(r + 8) * 1024 + cc) = o1;
        }
    }
}

// ---------------------------------------------------------------------------
// Kernel 2: scores[b,n,f,t] = (1/8) * sum_h q[b,f,n,h] * k[b,t,n,h]
// per (b,n): 1024x1024 GEMM, K=64. 64x64 block tile, 4x4 per thread.
// ---------------------------------------------------------------------------
__global__ __launch_bounds__(256)
void qk_kernel() {
    __shared__ float Qs[64][65];
    __shared__ float Ks[64][65];
    const int tid = threadIdx.x;
    const int tx = tid & 15, ty = tid >> 4;
    const int z = blockIdx.z;          // b*16 + n
    const int b = z >> 4, n = z & 15;
    const int f0 = blockIdx.y * 64, t0 = blockIdx.x * 64;

    const float* qb = g_q + ((size_t)(b * 1024 + f0) * 16 + n) * 64;
    const float* kb = g_k + ((size_t)(b * 1024 + t0) * 16 + n) * 64;

#pragma unroll
    for (int l = 0; l < 4; l++) {
        int i = tid + l * 256;
        int r = i >> 4, hq = (i & 15) << 2;
        float4 v = *(const float4*)(qb + (size_t)r * 1024 + hq);
        Qs[r][hq + 0] = v.x; Qs[r][hq + 1] = v.y;
        Qs[r][hq + 2] = v.z; Qs[r][hq + 3] = v.w;
        float4 w = *(const float4*)(kb + (size_t)r * 1024 + hq);
        Ks[r][hq + 0] = w.x; Ks[r][hq + 1] = w.y;
        Ks[r][hq + 2] = w.z; Ks[r][hq + 3] = w.w;
    }
    __syncthreads();

    float acc[4][4];
#pragma unroll
    for (int i = 0; i < 4; i++)
#pragma unroll
        for (int j = 0; j < 4; j++) acc[i][j] = 0.0f;

#pragma unroll
    for (int kk = 0; kk < 64; kk++) {
        float a[4], bb[4];
#pragma unroll
        for (int i = 0; i < 4; i++) a[i] = Qs[ty * 4 + i][kk];
#pragma unroll
        for (int j = 0; j < 4; j++) bb[j] = Ks[tx * 4 + j][kk];
#pragma unroll
        for (int i = 0; i < 4; i++)
#pragma unroll
            for (int j = 0; j < 4; j++) acc[i][j] = fmaf(a[i], bb[j], acc[i][j]);
    }

    float* cb = g_scores + ((size_t)z * 1024 + f0) * 1024 + t0;
#pragma unroll
    for (int i = 0; i < 4; i++) {
        float4 o;
        o.x = acc[i][0] * 0.125f; o.y = acc[i][1] * 0.125f;
        o.z = acc[i][2] * 0.125f; o.w = acc[i][3] * 0.125f;
        *(float4*)(cb + (size_t)(ty * 4 + i) * 1024 + tx * 4) = o;
    }
}

// ---------------------------------------------------------------------------
// Kernel 3: fused premix -> mask -> softmax -> postmix, in place on g_scores.
// ---------------------------------------------------------------------------
#define SW 1028
__global__ __launch_bounds__(256)
void mix_softmax_kernel(const int* __restrict__ amask,
                        const float* __restrict__ pre,
                        const float* __restrict__ post) {
    extern __shared__ float s[];           // 16 * SW floats
    __shared__ float wpre[256], wpost[256], sinv[16];
    const int tid = threadIdx.x;
    const int f = blockIdx.x, b = blockIdx.y;

    wpre[tid]  = pre[tid];
    wpost[tid] = post[tid];

    const size_t rowbase = ((size_t)(b * 16) * 1024 + f) * 1024;

#pragma unroll
    for (int n = 0; n < 16; n++) {
        float4 v = *(const float4*)(g_scores + rowbase + (size_t)n * 1048576 + tid * 4);
        *(float4*)(&s[n * SW + tid * 4]) = v;
    }
    __syncthreads();

    const int* mrow = amask + ((size_t)b * 1024 + f) * 1024;
#pragma unroll
    for (int c = 0; c < 4; c++) {
        int t = tid + c * 256;
        float x[16];
#pragma unroll
        for (int n = 0; n < 16; n++) x[n] = s[n * SW + t];
        float madd = (1.0f - (float)mrow[t]) * -10000.0f;
#pragma unroll
        for (int l = 0; l < 16; l++) {
            float y = madd;
#pragma unroll
            for (int n = 0; n < 16; n++) y = fmaf(x[n], wpre[n * 16 + l], y);
            s[l * SW + t] = y;
        }
    }
    __syncthreads();

    const int warp = tid >> 5, lane = tid & 31;
#pragma unroll
    for (int r = 0; r < 2; r++) {
        int l = warp * 2 + r;
        float m = -1e30f;
        for (int it = lane; it < 1024; it += 32) m = fmaxf(m, s[l * SW + it]);
#pragma unroll
        for (int o = 16; o > 0; o >>= 1) m = fmaxf(m, __shfl_xor_sync(0xffffffffu, m, o));
        float sum = 0.0f;
        for (int it = lane; it < 1024; it += 32) {
            float e = __expf(s[l * SW + it] - m);
            s[l * SW + it] = e;
            sum += e;
        }
#pragma unroll
        for (int o = 16; o > 0; o >>= 1) sum += __shfl_xor_sync(0xffffffffu, sum, o);
        if (lane == 0) sinv[l] = 1.0f / sum;
    }
    __syncthreads();

#pragma unroll
    for (int c = 0; c < 4; c++) {
        int t = tid + c * 256;
        float x[16];
#pragma unroll
        for (int n = 0; n < 16; n++) x[n] = s[n * SW + t] * sinv[n];
#pragma unroll
        for (int l = 0; l < 16; l++) {
            float y = 0.0f;
#pragma unroll
            for (int n = 0; n < 16; n++) y = fmaf(x[n], wpost[n * 16 + l], y);
            g_scores[rowbase + (size_t)l * 1048576 + t] = y;
        }
    }
}

// ---------------------------------------------------------------------------
// Kernel 4: ctx[b,f,n,h] = sum_t probs[b,n,f,t] * v[b,t,n,h]
// ---------------------------------------------------------------------------
__global__ __launch_bounds__(256)
void pv_kernel() {
    __shared__ float Ps[64][33];
    __shared__ float Vs[32][64];
    const int tid = threadIdx.x;
    const int tx = tid & 15, ty = tid >> 4;
    const int z = blockIdx.y, b = z >> 4, n = z & 15;
    const int f0 = blockIdx.x * 64;

    const float* pb = g_scores + ((size_t)z * 1024 + f0) * 1024;
    const float* vb = g_v + ((size_t)b * 1024 * 16 + n) * 64;   // + t*1024 + h

    float acc[4][4];
#pragma unroll
    for (int i = 0; i < 4; i++)
#pragma unroll
        for (int j = 0; j < 4; j++) acc[i][j] = 0.0f;

    for (int k0 = 0; k0 < 1024; k0 += 32) {
#pragma unroll
        for (int l = 0; l < 2; l++) {
            int i = tid + l * 256;
            int r = i >> 3, tq = (i & 7) << 2;
            float4 v = *(const float4*)(pb + (size_t)r * 1024 + k0 + tq);
            Ps[r][tq + 0] = v.x; Ps[r][tq + 1] = v.y;
            Ps[r][tq + 2] = v.z; Ps[r][tq + 3] = v.w;
        }
#pragma unroll
        for (int l = 0; l < 2; l++) {
            int i = tid + l * 256;
            int r = i >> 4, hq = (i & 15) << 2;
            *(float4*)(&Vs[r][hq]) =
                *(const float4*)(vb + (size_t)(k0 + r) * 1024 + hq);
        }
        __syncthreads();
#pragma unroll
        for (int kk = 0; kk < 32; kk++) {
            float a[4];
#pragma unroll
            for (int i = 0; i < 4; i++) a[i] = Ps[ty * 4 + i][kk];
            float4 bv4 = *(float4*)(&Vs[kk][tx * 4]);
#pragma unroll
            for (int i = 0; i < 4; i++) {
                acc[i][0] = fmaf(a[i], bv4.x, acc[i][0]);
                acc[i][1] = fmaf(a[i], bv4.y, acc[i][1]);
                acc[i][2] = fmaf(a[i], bv4.z, acc[i][2]);
                acc[i][3] = fmaf(a[i], bv4.w, acc[i][3]);
            }
        }
        __syncthreads();
    }

    float* cb = g_q + ((size_t)(b * 1024 + f0) * 16 + n) * 64;
#pragma unroll
    for (int i = 0; i < 4; i++) {
        float4 o;
        o.x = acc[i][0]; o.y = acc[i][1]; o.z = acc[i][2]; o.w = acc[i][3];
        *(float4*)(cb + (size_t)(ty * 4 + i) * 1024 + tx * 4) = o;
    }
}

// ---------------------------------------------------------------------------
extern "C" void kernel_launch(void* const* d_in, const int* in_sizes, int n_in,
                              void* d_out, int out_size) {
    const float* from  = (const float*)d_in[0];
    const float* to    = (const float*)d_in[1];
    const int*   amask = (const int*)d_in[2];
    const float* wq    = (const float*)d_in[3];
    const float* bq    = (const float*)d_in[4];
    const float* wk    = (const float*)d_in[5];
    const float* bk    = (const float*)d_in[6];
    const float* wv    = (const float*)d_in[7];
    const float* bv    = (const float*)d_in[8];
    const float* pre   = (const float*)d_in[9];
    const float* post  = (const float*)d_in[10];
    const float* wo    = (const float*)d_in[11];
    const float* bo    = (const float*)d_in[12];
    float* out = (float*)d_out;

    float *qp = nullptr, *kp = nullptr, *vp = nullptr;
    cudaGetSymbolAddress((void**)&qp, g_q);
    cudaGetSymbolAddress((void**)&kp, g_k);
    cudaGetSymbolAddress((void**)&vp, g_v);

    cudaFuncSetAttribute(mix_softmax_kernel,
                         cudaFuncAttributeMaxDynamicSharedMemorySize,
                         16 * SW * (int)sizeof(float));

    dim3 gG(8, 32);                         // N/128 x M/128
    mma_gemm_bias<<<gG, 256>>>(from, wq, bq, qp);
    mma_gemm_bias<<<gG, 256>>>(to,   wk, bk, kp);
    mma_gemm_bias<<<gG, 256>>>(to,   wv, bv, vp);

    qk_kernel<<<dim3(16, 16, 64), 256>>>();

    mix_softmax_kernel<<<dim3(1024, 4), 256, 16 * SW * (int)sizeof(float)>>>(
        amask, pre, post);

    pv_kernel<<<dim3(16, 64), 256>>>();

    mma_gemm_bias<<<gG, 256>>>(qp, wo, bo, out);
}

// round 4
// speedup vs baseline: 5.1506x; 4.3438x over previous
#include <cuda_runtime.h>
#include <cuda_bf16.h>
#include <cstdint>
#include <cstddef>

// ---------------- scratch (device globals: no cudaMalloc allowed) ----------
__device__ __nv_bfloat16 g_from_hi[4194304], g_from_lo[4194304];
__device__ __nv_bfloat16 g_to_hi[4194304],   g_to_lo[4194304];
__device__ __nv_bfloat16 g_wq_hi[1048576], g_wq_lo[1048576];
__device__ __nv_bfloat16 g_wk_hi[1048576], g_wk_lo[1048576];
__device__ __nv_bfloat16 g_wv_hi[1048576], g_wv_lo[1048576];
__device__ __nv_bfloat16 g_wo_hi[1048576], g_wo_lo[1048576];
__device__ __nv_bfloat16 g_q_hi[4194304], g_q_lo[4194304];
__device__ __nv_bfloat16 g_k_hi[4194304], g_k_lo[4194304];
__device__ __nv_bfloat16 g_v_hi[4194304], g_v_lo[4194304];
__device__ __nv_bfloat16 g_c_hi[4194304], g_c_lo[4194304];
__device__ float g_scores[67108864];                      // [B*N,S,S] fp32
__device__ __nv_bfloat16 g_p_hi[67108864], g_p_lo[67108864];

// ---------------------------------------------------------------------------
// PTX helpers
// ---------------------------------------------------------------------------
__device__ __forceinline__ uint32_t smem_u32(const void* p) {
    return (uint32_t)__cvta_generic_to_shared(p);
}
__device__ __forceinline__ void ldsm_x4(uint32_t* r, uint32_t addr) {
    asm volatile("ldmatrix.sync.aligned.m8n8.x4.shared.b16 {%0,%1,%2,%3}, [%4];"
                 : "=r"(r[0]), "=r"(r[1]), "=r"(r[2]), "=r"(r[3]) : "r"(addr));
}
__device__ __forceinline__ void ldsm_x4_t(uint32_t* r, uint32_t addr) {
    asm volatile("ldmatrix.sync.aligned.m8n8.x4.trans.shared.b16 {%0,%1,%2,%3}, [%4];"
                 : "=r"(r[0]), "=r"(r[1]), "=r"(r[2]), "=r"(r[3]) : "r"(addr));
}
__device__ __forceinline__ void mma_bf16(float* c, const uint32_t* a, const uint32_t* b) {
    asm volatile(
        "mma.sync.aligned.m16n8k16.row.col.f32.bf16.bf16.f32 "
        "{%0,%1,%2,%3}, {%4,%5,%6,%7}, {%8,%9}, {%0,%1,%2,%3};"
        : "+f"(c[0]), "+f"(c[1]), "+f"(c[2]), "+f"(c[3])
        : "r"(a[0]), "r"(a[1]), "r"(a[2]), "r"(a[3]), "r"(b[0]), "r"(b[1]));
}
__device__ __forceinline__ void split_bf16(float x, __nv_bfloat16& h, __nv_bfloat16& l) {
    h = __float2bfloat16(x);
    l = __float2bfloat16(x - __bfloat162float(h));
}
__device__ __forceinline__ void cp16(uint32_t dst, const void* src) {
    asm volatile("cp.async.cg.shared.global [%0], [%1], 16;\n" :: "r"(dst), "l"(src));
}
#define CP_COMMIT() asm volatile("cp.async.commit_group;\n")
#define CP_WAIT(n)  asm volatile("cp.async.wait_group %0;\n" :: "n"(n))

// ---------------------------------------------------------------------------
// split kernel: fp32 -> (hi, lo) bf16
// ---------------------------------------------------------------------------
__global__ void split_kernel(const float4* __restrict__ src,
                             uint2* __restrict__ hi, uint2* __restrict__ lo, int n4) {
    int i = blockIdx.x * blockDim.x + threadIdx.x;
    if (i >= n4) return;
    float4 v = src[i];
    __nv_bfloat16 h0, h1, h2, h3, l0, l1, l2, l3;
    split_bf16(v.x, h0, l0); split_bf16(v.y, h1, l1);
    split_bf16(v.z, h2, l2); split_bf16(v.w, h3, l3);
    __nv_bfloat162 a = __halves2bfloat162(h0, h1), b = __halves2bfloat162(h2, h3);
    __nv_bfloat162 c = __halves2bfloat162(l0, l1), d = __halves2bfloat162(l2, l3);
    hi[i] = make_uint2(*(uint32_t*)&a, *(uint32_t*)&b);
    lo[i] = make_uint2(*(uint32_t*)&c, *(uint32_t*)&d);
}

// ---------------------------------------------------------------------------
// GEMM: C[4096,1024] = A[4096,1024] @ W[1024,1024] + bias, bf16x3 MMA.
// A,W pre-split bf16. Block 128x128, BK=32, 8 warps (4m x 2n), double-buffered
// cp.async. SPLIT=true -> write (hi,lo) bf16; else fp32.
// dyn smem layout per stage (elems): Ahi@0 Alo@5120 Bhi@10240 Blo@14592 (18944)
// ---------------------------------------------------------------------------
#define G_PS 18944
__device__ __forceinline__ void gemm_stage(uint32_t sb,
        const __nv_bfloat16* Ahi, const __nv_bfloat16* Alo,
        const __nv_bfloat16* Bhi, const __nv_bfloat16* Blo,
        int row0, int col0, int k0, int tid) {
#pragma unroll
    for (int l = 0; l < 2; l++) {
        int idx = tid + l * 256;
        int m = idx >> 2, kc = (idx & 3) << 3;
        size_t so = (size_t)(row0 + m) * 1024 + k0 + kc;
        cp16(sb + (uint32_t)(m * 40 + kc) * 2, Ahi + so);
        cp16(sb + (uint32_t)(5120 + m * 40 + kc) * 2, Alo + so);
    }
#pragma unroll
    for (int l = 0; l < 2; l++) {
        int idx = tid + l * 256;
        int k = idx >> 4, nc = (idx & 15) << 3;
        size_t so = (size_t)(k0 + k) * 1024 + col0 + nc;
        cp16(sb + (uint32_t)(10240 + k * 136 + nc) * 2, Bhi + so);
        cp16(sb + (uint32_t)(14592 + k * 136 + nc) * 2, Blo + so);
    }
}

template <bool SPLIT>
__global__ __launch_bounds__(256, 2)
void gemm_bf16x3(const __nv_bfloat16* __restrict__ Ahi, const __nv_bfloat16* __restrict__ Alo,
                 const __nv_bfloat16* __restrict__ Bhi, const __nv_bfloat16* __restrict__ Blo,
                 const float* __restrict__ bias,
                 float* __restrict__ Cf,
                 __nv_bfloat16* __restrict__ Chi, __nv_bfloat16* __restrict__ Clo) {
    extern __shared__ __nv_bfloat16 dsm[];
    const int tid = threadIdx.x, lane = tid & 31, warp = tid >> 5;
    const int wm = warp >> 1, wn = warp & 1;
    const int row0 = blockIdx.y * 128, col0 = blockIdx.x * 128;
    const uint32_t sbase = smem_u32(dsm);

    float c[2][8][4];
#pragma unroll
    for (int i = 0; i < 2; i++)
#pragma unroll
        for (int j = 0; j < 8; j++)
#pragma unroll
            for (int q = 0; q < 4; q++) c[i][j][q] = 0.0f;

    gemm_stage(sbase, Ahi, Alo, Bhi, Blo, row0, col0, 0, tid);
    CP_COMMIT();

    const int lrow = lane & 15, koff = (lane >> 4) << 3;
    int st = 0;
    for (int k0 = 0; k0 < 1024; k0 += 32, st ^= 1) {
        if (k0 + 32 < 1024) {
            gemm_stage(sbase + (uint32_t)(st ^ 1) * G_PS * 2, Ahi, Alo, Bhi, Blo,
                       row0, col0, k0 + 32, tid);
            CP_COMMIT();
            CP_WAIT(1);
        } else {
            CP_WAIT(0);
        }
        __syncthreads();

        const uint32_t sb = sbase + (uint32_t)st * G_PS * 2;
#pragma unroll
        for (int ks = 0; ks < 2; ks++) {
            uint32_t ahi[2][4], alo[2][4];
#pragma unroll
            for (int mf = 0; mf < 2; mf++) {
                uint32_t off = (uint32_t)((wm * 32 + mf * 16 + lrow) * 40 + ks * 16 + koff) * 2;
                ldsm_x4(ahi[mf], sb + off);
                ldsm_x4(alo[mf], sb + 5120 * 2 + off);
            }
#pragma unroll
            for (int g = 0; g < 4; g++) {
                uint32_t bh[4], bl[4];
                uint32_t off = (uint32_t)((ks * 16 + lrow) * 136 + wn * 64 + g * 16 + koff) * 2;
                ldsm_x4_t(bh, sb + 10240 * 2 + off);
                ldsm_x4_t(bl, sb + 14592 * 2 + off);
#pragma unroll
                for (int h = 0; h < 2; h++) {
                    int nf = g * 2 + h;
#pragma unroll
                    for (int mf = 0; mf < 2; mf++) {
                        mma_bf16(c[mf][nf], ahi[mf], bh + h * 2);
                        mma_bf16(c[mf][nf], ahi[mf], bl + h * 2);
                        mma_bf16(c[mf][nf], alo[mf], bh + h * 2);
                    }
                }
            }
        }
        __syncthreads();
    }

    const int rbase = row0 + wm * 32 + (lane >> 2);
    const int cbase = col0 + wn * 64 + (lane & 3) * 2;
#pragma unroll
    for (int mf = 0; mf < 2; mf++) {
#pragma unroll
        for (int nf = 0; nf < 8; nf++) {
            int r = rbase + mf * 16;
            int cc = cbase + nf * 8;
            float2 bv = *(const float2*)(bias + cc);
            float v00 = c[mf][nf][0] + bv.x, v01 = c[mf][nf][1] + bv.y;
            float v10 = c[mf][nf][2] + bv.x, v11 = c[mf][nf][3] + bv.y;
            if (SPLIT) {
                __nv_bfloat16 h0, l0, h1, l1;
                split_bf16(v00, h0, l0); split_bf16(v01, h1, l1);
                *(__nv_bfloat162*)(Chi + (size_t)r * 1024 + cc) = __halves2bfloat162(h0, h1);
                *(__nv_bfloat162*)(Clo + (size_t)r * 1024 + cc) = __halves2bfloat162(l0, l1);
                split_bf16(v10, h0, l0); split_bf16(v11, h1, l1);
                *(__nv_bfloat162*)(Chi + (size_t)(r + 8) * 1024 + cc) = __halves2bfloat162(h0, h1);
                *(__nv_bfloat162*)(Clo + (size_t)(r + 8) * 1024 + cc) = __halves2bfloat162(l0, l1);
            } else {
                *(float2*)(Cf + (size_t)r * 1024 + cc)       = make_float2(v00, v01);
                *(float2*)(Cf + (size_t)(r + 8) * 1024 + cc) = make_float2(v10, v11);
            }
        }
    }
}

// ---------------------------------------------------------------------------
// qk: scores[z,f,t] = 0.125 * sum_h q[z..f][h] * k[z..t][h], bf16x3 MMA.
// Block = 128f x 128t, K=64 one-shot. q/k layout [(b*1024+s)*16+n]*64+h.
// dyn smem (elems): Qhi@0 Qlo@9216 Khi@18432 Klo@27648, stride 72.
// ---------------------------------------------------------------------------
__global__ __launch_bounds__(256)
void qk_mma() {
    extern __shared__ __nv_bfloat16 dsm[];
    const int tid = threadIdx.x, lane = tid & 31, warp = tid >> 5;
    const int wm = warp >> 1, wn = warp & 1;
    const int z = blockIdx.z, b = z >> 4, n = z & 15;
    const int t0 = blockIdx.x * 128, f0 = blockIdx.y * 128;
    const uint32_t sbase = smem_u32(dsm);

    const size_t qoff = ((size_t)(b * 1024 + f0) * 16 + n) * 64;
    const size_t koffg = ((size_t)(b * 1024 + t0) * 16 + n) * 64;

#pragma unroll
    for (int l = 0; l < 4; l++) {
        int idx = tid + l * 256;
        int m = idx >> 3, hc = (idx & 7) << 3;
        size_t so = (size_t)m * 1024 + hc;
        uint32_t doff = (uint32_t)(m * 72 + hc) * 2;
        cp16(sbase + doff,             g_q_hi + qoff + so);
        cp16(sbase + 9216 * 2 + doff,  g_q_lo + qoff + so);
        cp16(sbase + 18432 * 2 + doff, g_k_hi + koffg + so);
        cp16(sbase + 27648 * 2 + doff, g_k_lo + koffg + so);
    }
    CP_COMMIT();
    CP_WAIT(0);
    __syncthreads();

    float c[2][8][4];
#pragma unroll
    for (int i = 0; i < 2; i++)
#pragma unroll
        for (int j = 0; j < 8; j++)
#pragma unroll
            for (int q = 0; q < 4; q++) c[i][j][q] = 0.0f;

    const int lrow = lane & 15, koff = (lane >> 4) << 3;
#pragma unroll
    for (int ks = 0; ks < 4; ks++) {
        uint32_t ahi[2][4], alo[2][4];
#pragma unroll
        for (int mf = 0; mf < 2; mf++) {
            uint32_t off = (uint32_t)((wm * 32 + mf * 16 + lrow) * 72 + ks * 16 + koff) * 2;
            ldsm_x4(ahi[mf], sbase + off);
            ldsm_x4(alo[mf], sbase + 9216 * 2 + off);
        }
#pragma unroll
        for (int g = 0; g < 4; g++) {
            // K stored [t][h] = [n][k] row-major -> NON-trans ldsm, regroup:
            // regs (n0,k0),(n8,k0),(n0,k8),(n8,k8) -> b(n0)={r0,r2}, b(n8)={r1,r3}
            uint32_t rh[4], rl[4];
            uint32_t off = (uint32_t)((wn * 64 + g * 16 + lrow) * 72 + ks * 16 + koff) * 2;
            ldsm_x4(rh, sbase + 18432 * 2 + off);
            ldsm_x4(rl, sbase + 27648 * 2 + off);
            uint32_t bh0[2] = {rh[0], rh[2]}, bh1[2] = {rh[1], rh[3]};
            uint32_t bl0[2] = {rl[0], rl[2]}, bl1[2] = {rl[1], rl[3]};
#pragma unroll
            for (int mf = 0; mf < 2; mf++) {
                mma_bf16(c[mf][g * 2 + 0], ahi[mf], bh0);
                mma_bf16(c[mf][g * 2 + 0], ahi[mf], bl0);
                mma_bf16(c[mf][g * 2 + 0], alo[mf], bh0);
                mma_bf16(c[mf][g * 2 + 1], ahi[mf], bh1);
                mma_bf16(c[mf][g * 2 + 1], ahi[mf], bl1);
                mma_bf16(c[mf][g * 2 + 1], alo[mf], bh1);
            }
        }
    }

    float* out = g_scores + (size_t)z * 1048576;
    const int rbase = f0 + wm * 32 + (lane >> 2);
    const int cbase = t0 + wn * 64 + (lane & 3) * 2;
#pragma unroll
    for (int mf = 0; mf < 2; mf++) {
#pragma unroll
        for (int nf = 0; nf < 8; nf++) {
            int r = rbase + mf * 16, cc = cbase + nf * 8;
            *(float2*)(out + (size_t)r * 1024 + cc) =
                make_float2(c[mf][nf][0] * 0.125f, c[mf][nf][1] * 0.125f);
            *(float2*)(out + (size_t)(r + 8) * 1024 + cc) =
                make_float2(c[mf][nf][2] * 0.125f, c[mf][nf][3] * 0.125f);
        }
    }
}

// ---------------------------------------------------------------------------
// fused premix -> mask -> softmax -> postmix; reads fp32 scores,
// writes split-bf16 probs.
// ---------------------------------------------------------------------------
#define SW 1028
__global__ __launch_bounds__(256)
void mix_softmax_kernel(const int* __restrict__ amask,
                        const float* __restrict__ pre,
                        const float* __restrict__ post) {
    extern __shared__ float s[];            // 16 * SW floats
    __shared__ float wpre[256], wpost[256], sinv[16];
    const int tid = threadIdx.x;
    const int f = blockIdx.x, b = blockIdx.y;

    wpre[tid]  = pre[tid];
    wpost[tid] = post[tid];

    const size_t rowbase = ((size_t)(b * 16) * 1024 + f) * 1024;

#pragma unroll
    for (int n = 0; n < 16; n++) {
        float4 v = *(const float4*)(g_scores + rowbase + (size_t)n * 1048576 + tid * 4);
        *(float4*)(&s[n * SW + tid * 4]) = v;
    }
    __syncthreads();

    const int* mrow = amask + ((size_t)b * 1024 + f) * 1024;
#pragma unroll
    for (int c = 0; c < 4; c++) {
        int t = tid + c * 256;
        float x[16];
#pragma unroll
        for (int n = 0; n < 16; n++) x[n] = s[n * SW + t];
        float madd = (1.0f - (float)mrow[t]) * -10000.0f;
#pragma unroll
        for (int l = 0; l < 16; l++) {
            float y = madd;
#pragma unroll
            for (int n = 0; n < 16; n++) y = fmaf(x[n], wpre[n * 16 + l], y);
            s[l * SW + t] = y;
        }
    }
    __syncthreads();

    const int warp = tid >> 5, lane = tid & 31;
#pragma unroll
    for (int r = 0; r < 2; r++) {
        int l = warp * 2 + r;
        float m = -1e30f;
        for (int it = lane; it < 1024; it += 32) m = fmaxf(m, s[l * SW + it]);
#pragma unroll
        for (int o = 16; o > 0; o >>= 1) m = fmaxf(m, __shfl_xor_sync(0xffffffffu, m, o));
        float sum = 0.0f;
        for (int it = lane; it < 1024; it += 32) {
            float e = __expf(s[l * SW + it] - m);
            s[l * SW + it] = e;
            sum += e;
        }
#pragma unroll
        for (int o = 16; o > 0; o >>= 1) sum += __shfl_xor_sync(0xffffffffu, sum, o);
        if (lane == 0) sinv[l] = 1.0f / sum;
    }
    __syncthreads();

#pragma unroll
    for (int c = 0; c < 2; c++) {
        int t = (tid + c * 256) * 2;
        float x0[16], x1[16];
#pragma unroll
        for (int n = 0; n < 16; n++) {
            x0[n] = s[n * SW + t] * sinv[n];
            x1[n] = s[n * SW + t + 1] * sinv[n];
        }
#pragma unroll
        for (int l = 0; l < 16; l++) {
            float y0 = 0.0f, y1 = 0.0f;
#pragma unroll
            for (int n = 0; n < 16; n++) {
                y0 = fmaf(x0[n], wpost[n * 16 + l], y0);
                y1 = fmaf(x1[n], wpost[n * 16 + l], y1);
            }
            __nv_bfloat16 h0, l0, h1, l1;
            split_bf16(y0, h0, l0); split_bf16(y1, h1, l1);
            size_t base = rowbase + (size_t)l * 1048576 + t;
            *(__nv_bfloat162*)(g_p_hi + base) = __halves2bfloat162(h0, h1);
            *(__nv_bfloat162*)(g_p_lo + base) = __halves2bfloat162(l0, l1);
        }
    }
}

// ---------------------------------------------------------------------------
// pv: ctx[b,f,n,h] = sum_t P[z,f,t] * v[b,t,n,h], bf16x3 MMA.
// Block = 128f x 64h, BK=32, double-buffered. 8 warps (4m x 2n), warp 32x32.
// dyn smem per stage (elems): Phi@0 Plo@5120 Vhi@10240 Vlo@12544 (14848).
// ---------------------------------------------------------------------------
#define PV_PS 14848
__device__ __forceinline__ void pv_stage(uint32_t sb, size_t pbase, size_t vbase,
                                         int k0, int tid) {
#pragma unroll
    for (int l = 0; l < 2; l++) {
        int idx = tid + l * 256;
        int m = idx >> 2, tc = (idx & 3) << 3;
        size_t so = pbase + (size_t)m * 1024 + k0 + tc;
        cp16(sb + (uint32_t)(m * 40 + tc) * 2, g_p_hi + so);
        cp16(sb + (uint32_t)(5120 + m * 40 + tc) * 2, g_p_lo + so);
    }
    {
        int tr = tid >> 3, hc = (tid & 7) << 3;
        size_t so = vbase + (size_t)(k0 + tr) * 1024 + hc;
        cp16(sb + (uint32_t)(10240 + tr * 72 + hc) * 2, g_v_hi + so);
        cp16(sb + (uint32_t)(12544 + tr * 72 + hc) * 2, g_v_lo + so);
    }
}

__global__ __launch_bounds__(256)
void pv_mma() {
    extern __shared__ __nv_bfloat16 dsm[];
    const int tid = threadIdx.x, lane = tid & 31, warp = tid >> 5;
    const int wm = warp >> 1, wn = warp & 1;
    const int z = blockIdx.y, b = z >> 4, n = z & 15;
    const int f0 = blockIdx.x * 128;
    const uint32_t sbase = smem_u32(dsm);

    const size_t pbase = (size_t)z * 1048576 + (size_t)f0 * 1024;
    const size_t vbase = (size_t)(b * 1024) * 1024 + (size_t)n * 64;   // + t*1024 + h

    float c[2][4][4];
#pragma unroll
    for (int i = 0; i < 2; i++)
#pragma unroll
        for (int j = 0; j < 4; j++)
#pragma unroll
            for (int q = 0; q < 4; q++) c[i][j][q] = 0.0f;

    pv_stage(sbase, pbase, vbase, 0, tid);
    CP_COMMIT();

    const int lrow = lane & 15, koff = (lane >> 4) << 3;
    int st = 0;
    for (int k0 = 0; k0 < 1024; k0 += 32, st ^= 1) {
        if (k0 + 32 < 1024) {
            pv_stage(sbase + (uint32_t)(st ^ 1) * PV_PS * 2, pbase, vbase, k0 + 32, tid);
            CP_COMMIT();
            CP_WAIT(1);
        } else {
            CP_WAIT(0);
        }
        __syncthreads();

        const uint32_t sb = sbase + (uint32_t)st * PV_PS * 2;
#pragma unroll
        for (int ks = 0; ks < 2; ks++) {
            uint32_t ahi[2][4], alo[2][4];
#pragma unroll
            for (int mf = 0; mf < 2; mf++) {
                uint32_t off = (uint32_t)((wm * 32 + mf * 16 + lrow) * 40 + ks * 16 + koff) * 2;
                ldsm_x4(ahi[mf], sb + off);
                ldsm_x4(alo[mf], sb + 5120 * 2 + off);
            }
#pragma unroll
            for (int g = 0; g < 2; g++) {
                uint32_t bh[4], bl[4];
                uint32_t off = (uint32_t)((ks * 16 + lrow) * 72 + wn * 32 + g * 16 + koff) * 2;
                ldsm_x4_t(bh, sb + 10240 * 2 + off);
                ldsm_x4_t(bl, sb + 12544 * 2 + off);
#pragma unroll
                for (int h = 0; h < 2; h++) {
                    int nf = g * 2 + h;
#pragma unroll
                    for (int mf = 0; mf < 2; mf++) {
                        mma_bf16(c[mf][nf], ahi[mf], bh + h * 2);
                        mma_bf16(c[mf][nf], ahi[mf], bl + h * 2);
                        mma_bf16(c[mf][nf], alo[mf], bh + h * 2);
                    }
                }
            }
        }
        __syncthreads();
    }

    // epilogue: split ctx -> g_c_hi/lo at [(b*1024+f)*16+n]*64 + h
    const int rbase = f0 + wm * 32 + (lane >> 2);
    const int cbase = wn * 32 + (lane & 3) * 2;
#pragma unroll
    for (int mf = 0; mf < 2; mf++) {
#pragma unroll
        for (int nf = 0; nf < 4; nf++) {
            int r = rbase + mf * 16, cc = cbase + nf * 8;
            size_t o0 = ((size_t)(b * 1024 + r) * 16 + n) * 64 + cc;
            size_t o1 = ((size_t)(b * 1024 + r + 8) * 16 + n) * 64 + cc;
            __nv_bfloat16 h0, l0, h1, l1;
            split_bf16(c[mf][nf][0], h0, l0); split_bf16(c[mf][nf][1], h1, l1);
            *(__nv_bfloat162*)(g_c_hi + o0) = __halves2bfloat162(h0, h1);
            *(__nv_bfloat162*)(g_c_lo + o0) = __halves2bfloat162(l0, l1);
            split_bf16(c[mf][nf][2], h0, l0); split_bf16(c[mf][nf][3], h1, l1);
            *(__nv_bfloat162*)(g_c_hi + o1) = __halves2bfloat162(h0, h1);
            *(__nv_bfloat162*)(g_c_lo + o1) = __halves2bfloat162(l0, l1);
        }
    }
}

// ---------------------------------------------------------------------------
extern "C" void kernel_launch(void* const* d_in, const int* in_sizes, int n_in,
                              void* d_out, int out_size) {
    const float* from  = (const float*)d_in[0];
    const float* to    = (const float*)d_in[1];
    const int*   amask = (const int*)d_in[2];
    const float* wq    = (const float*)d_in[3];
    const float* bq    = (const float*)d_in[4];
    const float* wk    = (const float*)d_in[5];
    const float* bk    = (const float*)d_in[6];
    const float* wv    = (const float*)d_in[7];
    const float* bv    = (const float*)d_in[8];
    const float* pre   = (const float*)d_in[9];
    const float* post  = (const float*)d_in[10];
    const float* wo    = (const float*)d_in[11];
    const float* bo    = (const float*)d_in[12];
    float* out = (float*)d_out;

    void *fh, *fl, *th, *tl, *qwh, *qwl, *kwh, *kwl, *vwh, *vwl, *owh, *owl;
    void *qh, *ql, *kh, *kl, *vh, *vl, *ch, *cl;
    cudaGetSymbolAddress(&fh, g_from_hi); cudaGetSymbolAddress(&fl, g_from_lo);
    cudaGetSymbolAddress(&th, g_to_hi);   cudaGetSymbolAddress(&tl, g_to_lo);
    cudaGetSymbolAddress(&qwh, g_wq_hi);  cudaGetSymbolAddress(&qwl, g_wq_lo);
    cudaGetSymbolAddress(&kwh, g_wk_hi);  cudaGetSymbolAddress(&kwl, g_wk_lo);
    cudaGetSymbolAddress(&vwh, g_wv_hi);  cudaGetSymbolAddress(&vwl, g_wv_lo);
    cudaGetSymbolAddress(&owh, g_wo_hi);  cudaGetSymbolAddress(&owl, g_wo_lo);
    cudaGetSymbolAddress(&qh, g_q_hi);    cudaGetSymbolAddress(&ql, g_q_lo);
    cudaGetSymbolAddress(&kh, g_k_hi);    cudaGetSymbolAddress(&kl, g_k_lo);
    cudaGetSymbolAddress(&vh, g_v_hi);    cudaGetSymbolAddress(&vl, g_v_lo);
    cudaGetSymbolAddress(&ch, g_c_hi);    cudaGetSymbolAddress(&cl, g_c_lo);

    const int GEMM_SMEM = 2 * G_PS * 2;       // 75776 B
    const int QK_SMEM   = 36864 * 2;          // 73728 B
    const int PV_SMEM   = 2 * PV_PS * 2;      // 59392 B
    const int SMX_SMEM  = 16 * SW * 4;        // 65792 B
    cudaFuncSetAttribute(gemm_bf16x3<true>,  cudaFuncAttributeMaxDynamicSharedMemorySize, GEMM_SMEM);
    cudaFuncSetAttribute(gemm_bf16x3<false>, cudaFuncAttributeMaxDynamicSharedMemorySize, GEMM_SMEM);
    cudaFuncSetAttribute(qk_mma,             cudaFuncAttributeMaxDynamicSharedMemorySize, QK_SMEM);
    cudaFuncSetAttribute(pv_mma,             cudaFuncAttributeMaxDynamicSharedMemorySize, PV_SMEM);
    cudaFuncSetAttribute(mix_softmax_kernel, cudaFuncAttributeMaxDynamicSharedMemorySize, SMX_SMEM);

    // split inputs + weights
    split_kernel<<<4096, 256>>>((const float4*)from, (uint2*)fh, (uint2*)fl, 1048576);
    split_kernel<<<4096, 256>>>((const float4*)to,   (uint2*)th, (uint2*)tl, 1048576);
    split_kernel<<<1024, 256>>>((const float4*)wq, (uint2*)qwh, (uint2*)qwl, 262144);
    split_kernel<<<1024, 256>>>((const float4*)wk, (uint2*)kwh, (uint2*)kwl, 262144);
    split_kernel<<<1024, 256>>>((const float4*)wv, (uint2*)vwh, (uint2*)vwl, 262144);
    split_kernel<<<1024, 256>>>((const float4*)wo, (uint2*)owh, (uint2*)owl, 262144);

    dim3 gG(8, 32);
    gemm_bf16x3<true><<<gG, 256, GEMM_SMEM>>>(
        (const __nv_bfloat16*)fh, (const __nv_bfloat16*)fl,
        (const __nv_bfloat16*)qwh, (const __nv_bfloat16*)qwl, bq,
        nullptr, (__nv_bfloat16*)qh, (__nv_bfloat16*)ql);
    gemm_bf16x3<true><<<gG, 256, GEMM_SMEM>>>(
        (const __nv_bfloat16*)th, (const __nv_bfloat16*)tl,
        (const __nv_bfloat16*)kwh, (const __nv_bfloat16*)kwl, bk,
        nullptr, (__nv_bfloat16*)kh, (__nv_bfloat16*)kl);
    gemm_bf16x3<true><<<gG, 256, GEMM_SMEM>>>(
        (const __nv_bfloat16*)th, (const __nv_bfloat16*)tl,
        (const __nv_bfloat16*)vwh, (const __nv_bfloat16*)vwl, bv,
        nullptr, (__nv_bfloat16*)vh, (__nv_bfloat16*)vl);

    qk_mma<<<dim3(8, 8, 64), 256, QK_SMEM>>>();

    mix_softmax_kernel<<<dim3(1024, 4), 256, SMX_SMEM>>>(amask, pre, post);

    pv_mma<<<dim3(8, 64), 256, PV_SMEM>>>();

    gemm_bf16x3<false><<<gG, 256, GEMM_SMEM>>>(
        (const __nv_bfloat16*)ch, (const __nv_bfloat16*)cl,
        (const __nv_bfloat16*)owh, (const __nv_bfloat16*)owl, bo,
        out, nullptr, nullptr);
}